// round 6
// baseline (speedup 1.0000x reference)
#include <cuda_runtime.h>
#include <math.h>

// ---------------- problem constants ----------------
#define DN     160
#define MS     64
#define MV     32
#define NGROUP 16
#define FCIN   128
#define MAXN   10000
#define MAXE   320000
#define EPB    8

#define INV8        0.125f
#define INV16       0.0625f
#define INV_SQRT32  0.17677669529663687f
#define INV_SQRT128 0.08838834764831845f
#define INV_SQRT3   0.5773502691896258f
#define INV_FAN     0.05892556509887896f
#define LN_EPS      1e-5f

// ---------------- device scratch ----------------
__device__ float g_scs[MAXN * MS];
__device__ float g_scv[MAXN * MV * 3];
__device__ float g_ns [MAXN * MS];
__device__ float g_nv [MAXN * MV * 3];
__device__ float g_ps [MAXN * MS];
__device__ float g_pv [MAXN * MV * 3];
__device__ float g_stats[NGROUP * 4];
__device__ float g_norm [NGROUP * 3];

// per-node precomputed partials {P_c0,P_c1,P_c2, A}
__device__ float4 g_zsI[MAXN * 64];
__device__ float4 g_zsJ[MAXN * 64];
__device__ float4 g_zgI[MAXN * 32];
__device__ float4 g_zgJ[MAXN * 32];
__device__ float4 g_svI[MAXN * 32];
__device__ float4 g_svJ[MAXN * 32];

// per-edge GEMM outputs
__device__ float g_WFC[(size_t)MAXE * 96];
__device__ float g_Ces[(size_t)MAXE * 128];
__device__ float g_Cdd[(size_t)MAXE * 96];
// concatenated weights
__device__ float g_Wes[64 * 128];
__device__ float g_Wdd[32 * 96];

__device__ __forceinline__ float silu_f(float x) { return x / (1.f + __expf(-x)); }
__device__ __forceinline__ float sigm_f(float x) { return 1.f / (1.f + __expf(-x)); }

__device__ __forceinline__ unsigned int f2tf32(float x) {
    unsigned int r;
    asm("cvt.rna.tf32.f32 %0, %1;" : "=r"(r) : "f"(x));
    return r;
}
__device__ __forceinline__ void mma8(float* c, unsigned int a0, unsigned int a1,
                                     unsigned int a2, unsigned int a3,
                                     unsigned int b0, unsigned int b1) {
    asm volatile(
        "mma.sync.aligned.m16n8k8.row.col.f32.tf32.tf32.f32 "
        "{%0,%1,%2,%3}, {%4,%5,%6,%7}, {%8,%9}, {%0,%1,%2,%3};"
        : "+f"(c[0]), "+f"(c[1]), "+f"(c[2]), "+f"(c[3])
        : "r"(a0), "r"(a1), "r"(a2), "r"(a3), "r"(b0), "r"(b1));
}

// load W[K][N] into smem as hi/lo tf32, layout [N][K+4]
template<int K, int N>
__device__ __forceinline__ void load_w(unsigned* wHi, unsigned* wLo,
                                       const float* __restrict__ W, int t) {
    constexpr int KP = K + 4;
    for (int idx = t; idx < K * N; idx += 128) {
        int k = idx / N, n = idx - k * N;
        float w = W[idx];
        unsigned hi = f2tf32(w);
        wHi[n * KP + k] = hi;
        wLo[n * KP + k] = f2tf32(w - __uint_as_float(hi));
    }
}

// 3xTF32 accumulate: rows A0 (r), A1 (r+8), contiguous cols
template<int K, int NB>
__device__ __forceinline__ void mma_stage(const unsigned* __restrict__ wHi,
                                          const unsigned* __restrict__ wLo,
                                          const float* __restrict__ A0,
                                          const float* __restrict__ A1,
                                          float acc[NB][4], int lane) {
    constexpr int KP = K + 4;
    #pragma unroll
    for (int kb = 0; kb < K / 8; kb++) {
        const int c = kb * 8 + (lane & 3);
        float a0 = A0[c],     a1 = A1[c];
        float a2 = A0[c + 4], a3 = A1[c + 4];
        unsigned h0 = f2tf32(a0), h1 = f2tf32(a1), h2 = f2tf32(a2), h3 = f2tf32(a3);
        unsigned l0 = f2tf32(a0 - __uint_as_float(h0));
        unsigned l1 = f2tf32(a1 - __uint_as_float(h1));
        unsigned l2 = f2tf32(a2 - __uint_as_float(h2));
        unsigned l3 = f2tf32(a3 - __uint_as_float(h3));
        const int koff = kb * 8 + (lane & 3);
        const int nbase = lane >> 2;
        #pragma unroll
        for (int nb = 0; nb < NB; nb++) {
            int off = (nb * 8 + nbase) * KP + koff;
            unsigned bh0 = wHi[off], bh1 = wHi[off + 4];
            unsigned bl0 = wLo[off], bl1 = wLo[off + 4];
            mma8(acc[nb], h0, h1, h2, h3, bh0, bh1);
            mma8(acc[nb], l0, l1, l2, l3, bh0, bh1);
            mma8(acc[nb], h0, h1, h2, h3, bl0, bl1);
        }
    }
}

// ---------------- zero scratch ----------------
__global__ void k_zero(int N) {
    int tot = N * DN + NGROUP * 4;
    for (int i = blockIdx.x * blockDim.x + threadIdx.x; i < tot; i += gridDim.x * blockDim.x) {
        if (i < N * MS)      g_ns[i] = 0.f;
        else if (i < N * DN) g_nv[i - N * MS] = 0.f;
        else                 g_stats[i - N * DN] = 0.f;
    }
}

// ---------------- concat-weight prep ----------------
__global__ void k_prepW(const float* __restrict__ Wss0, const float* __restrict__ Wssg,
                        const float* __restrict__ Wsv1, const float* __restrict__ Wvv0,
                        const float* __restrict__ Wvvg) {
    int t = blockIdx.x * blockDim.x + threadIdx.x;
    if (t < 64 * 128) {
        int u = t >> 7, n = t & 127;
        float v;
        if (n < 64)      v = Wss0[(128 + u) * 64 + n];
        else if (n < 96) v = Wssg[(128 + u) * 32 + (n - 64)];
        else             v = Wsv1[(128 + u) * 32 + (n - 96)];
        g_Wes[t] = v;
    } else if (t < 64 * 128 + 32 * 96) {
        int i = t - 64 * 128;
        int u = i / 96, n = i - u * 96;
        g_Wdd[i] = (n < 64) ? Wvv0[(64 + u) * 64 + n] : Wvvg[(64 + u) * 32 + (n - 64)];
    }
}

// ---------------- fused fc chain: ele -> H1 -> H2 -> WFC ----------------
__global__ void __launch_bounds__(128) k_fc(
    const float* __restrict__ ele,
    const float* __restrict__ fW1, const float* __restrict__ fb1,
    const float* __restrict__ fW2, const float* __restrict__ fb2,
    const float* __restrict__ fW3, const float* __restrict__ fb3,
    int E)
{
    extern __shared__ unsigned smraw[];
    unsigned* wHi = smraw;                 // max 64*132 = 8448
    unsigned* wLo = smraw + 8448;
    float* H1 = (float*)(smraw + 16896);   // [4 warps][16][68]
    float* H2 = H1 + 4 * 16 * 68;

    const int t = threadIdx.x;
    const int lane = t & 31, warp = t >> 5;
    const int r0 = blockIdx.x * 64 + warp * 16 + (lane >> 2);
    const int r1 = r0 + 8;

    float* h1r0 = H1 + warp * 16 * 68 + (lane >> 2) * 68;
    float* h1r1 = h1r0 + 8 * 68;
    float* h2r0 = H2 + warp * 16 * 68 + (lane >> 2) * 68;
    float* h2r1 = h2r0 + 8 * 68;

    // ---- stage 1: fc1 [128 -> 64] silu ----
    load_w<128, 64>(wHi, wLo, fW1, t);
    __syncthreads();
    {
        const float* A0 = ele + (long)min(r0, E - 1) * FCIN;
        const float* A1 = ele + (long)min(r1, E - 1) * FCIN;
        float acc[8][4];
        #pragma unroll
        for (int nb = 0; nb < 8; nb++) { acc[nb][0]=0.f; acc[nb][1]=0.f; acc[nb][2]=0.f; acc[nb][3]=0.f; }
        mma_stage<128, 8>(wHi, wLo, A0, A1, acc, lane);
        #pragma unroll
        for (int nb = 0; nb < 8; nb++) {
            int n = nb * 8 + 2 * (lane & 3);
            float b0 = __ldg(&fb1[n]), b1 = __ldg(&fb1[n + 1]);
            h1r0[n]     = silu_f(acc[nb][0] + b0);
            h1r0[n + 1] = silu_f(acc[nb][1] + b1);
            h1r1[n]     = silu_f(acc[nb][2] + b0);
            h1r1[n + 1] = silu_f(acc[nb][3] + b1);
        }
    }
    __syncthreads();

    // ---- stage 2: fc2 [64 -> 64] silu ----
    load_w<64, 64>(wHi, wLo, fW2, t);
    __syncthreads();
    {
        float acc[8][4];
        #pragma unroll
        for (int nb = 0; nb < 8; nb++) { acc[nb][0]=0.f; acc[nb][1]=0.f; acc[nb][2]=0.f; acc[nb][3]=0.f; }
        mma_stage<64, 8>(wHi, wLo, h1r0, h1r1, acc, lane);
        #pragma unroll
        for (int nb = 0; nb < 8; nb++) {
            int n = nb * 8 + 2 * (lane & 3);
            float b0 = __ldg(&fb2[n]), b1 = __ldg(&fb2[n + 1]);
            h2r0[n]     = silu_f(acc[nb][0] + b0);
            h2r0[n + 1] = silu_f(acc[nb][1] + b1);
            h2r1[n]     = silu_f(acc[nb][2] + b0);
            h2r1[n + 1] = silu_f(acc[nb][3] + b1);
        }
    }
    __syncthreads();

    // ---- stage 3: fc3 [64 -> 96] ----
    load_w<64, 96>(wHi, wLo, fW3, t);
    __syncthreads();
    {
        float acc[12][4];
        #pragma unroll
        for (int nb = 0; nb < 12; nb++) { acc[nb][0]=0.f; acc[nb][1]=0.f; acc[nb][2]=0.f; acc[nb][3]=0.f; }
        mma_stage<64, 12>(wHi, wLo, h2r0, h2r1, acc, lane);
        #pragma unroll
        for (int nb = 0; nb < 12; nb++) {
            int n = nb * 8 + 2 * (lane & 3);
            float b0 = __ldg(&fb3[n]), b1 = __ldg(&fb3[n + 1]);
            if (r0 < E) *reinterpret_cast<float2*>(&g_WFC[(long)r0 * 96 + n]) =
                make_float2(acc[nb][0] + b0, acc[nb][1] + b1);
            if (r1 < E) *reinterpret_cast<float2*>(&g_WFC[(long)r1 * 96 + n]) =
                make_float2(acc[nb][2] + b0, acc[nb][3] + b1);
        }
    }
}

// ---------------- fused es/dd GEMMs: edge_fea/sh -> Ces, Cdd ----------------
__global__ void __launch_bounds__(128) k_esdd(
    const float* __restrict__ edge_fea, const float* __restrict__ edge_sh, int E)
{
    extern __shared__ unsigned smraw[];
    unsigned* wHi = smraw;                 // max 128*68 = 8704
    unsigned* wLo = smraw + 8704;
    float* DD = (float*)(smraw + 17408);   // [64][36]

    const int t = threadIdx.x;
    const int lane = t & 31, warp = t >> 5;
    const int e0 = blockIdx.x * 64;
    const int r0 = e0 + warp * 16 + (lane >> 2);
    const int r1 = r0 + 8;

    // ---- dd tile: DD[e][u] = <ev[e,u,:], sh1>/sqrt3 ----
    for (int idx = t; idx < 64 * 32; idx += 128) {
        int e = idx >> 5, u = idx & 31;
        int eg = e0 + e;
        float v = 0.f;
        if (eg < E) {
            const float* ev = edge_fea + (size_t)eg * DN + 64 + u * 3;
            v = (ev[0] * edge_sh[eg * 4 + 1] + ev[1] * edge_sh[eg * 4 + 2] +
                 ev[2] * edge_sh[eg * 4 + 3]) * INV_SQRT3;
        }
        DD[e * 36 + u] = v;
    }
    __syncthreads();

    // ---- stage 1: Ces = es @ Wes [64 -> 128] ----
    load_w<64, 128>(wHi, wLo, g_Wes, t);
    __syncthreads();
    {
        const float* A0 = edge_fea + (size_t)min(r0, E - 1) * DN;
        const float* A1 = edge_fea + (size_t)min(r1, E - 1) * DN;
        float acc[16][4];
        #pragma unroll
        for (int nb = 0; nb < 16; nb++) { acc[nb][0]=0.f; acc[nb][1]=0.f; acc[nb][2]=0.f; acc[nb][3]=0.f; }
        mma_stage<64, 16>(wHi, wLo, A0, A1, acc, lane);
        #pragma unroll
        for (int nb = 0; nb < 16; nb++) {
            int n = nb * 8 + 2 * (lane & 3);
            if (r0 < E) *reinterpret_cast<float2*>(&g_Ces[(long)r0 * 128 + n]) =
                make_float2(acc[nb][0], acc[nb][1]);
            if (r1 < E) *reinterpret_cast<float2*>(&g_Ces[(long)r1 * 128 + n]) =
                make_float2(acc[nb][2], acc[nb][3]);
        }
    }
    __syncthreads();

    // ---- stage 2: Cdd = DD @ Wdd [32 -> 96] ----
    load_w<32, 96>(wHi, wLo, g_Wdd, t);
    __syncthreads();
    {
        const float* A0 = DD + (warp * 16 + (lane >> 2)) * 36;
        const float* A1 = A0 + 8 * 36;
        float acc[12][4];
        #pragma unroll
        for (int nb = 0; nb < 12; nb++) { acc[nb][0]=0.f; acc[nb][1]=0.f; acc[nb][2]=0.f; acc[nb][3]=0.f; }
        mma_stage<32, 12>(wHi, wLo, A0, A1, acc, lane);
        #pragma unroll
        for (int nb = 0; nb < 12; nb++) {
            int n = nb * 8 + 2 * (lane & 3);
            if (r0 < E) *reinterpret_cast<float2*>(&g_Cdd[(long)r0 * 96 + n]) =
                make_float2(acc[nb][0], acc[nb][1]);
            if (r1 < E) *reinterpret_cast<float2*>(&g_Cdd[(long)r1 * 96 + n]) =
                make_float2(acc[nb][2], acc[nb][3]);
        }
    }
}

// ---------------- node pre (unchanged) ----------------
__global__ __launch_bounds__(128) void k_node_pre(
    const float* __restrict__ nf, const float* __restrict__ onehot,
    const float* __restrict__ lpWs, const float* __restrict__ lpbs,
    const float* __restrict__ lpWv,
    const float* __restrict__ scWs, const float* __restrict__ scWv,
    const float* __restrict__ Wss0, const float* __restrict__ Wvv0,
    const float* __restrict__ Wssg, const float* __restrict__ Wvvg,
    const float* __restrict__ Wsv1, const float* __restrict__ Wvs1)
{
    const int n = blockIdx.x;
    const int t = threadIdx.x;
    __shared__ float sIn[MS];
    __shared__ float vIn[MV * 3];
    __shared__ float sO [MS];
    __shared__ float vO [MV * 3];
    __shared__ int ssp;

    if (t < MS) sIn[t] = nf[n * DN + t];
    if (t < 96) vIn[t] = nf[n * DN + MS + t];
    if (t == 0) {
        int sp = 0; float best = onehot[n * 4];
        #pragma unroll
        for (int k = 1; k < 4; k++) { float v = onehot[n * 4 + k]; if (v > best) { best = v; sp = k; } }
        ssp = sp;
    }
    __syncthreads();
    const int sp = ssp;

    if (t < MS) {
        float a = 0.f, b = 0.f;
        #pragma unroll 8
        for (int u = 0; u < MS; u++) {
            float x = sIn[u];
            a += x * lpWs[u * MS + t];
            b += x * scWs[(u * 4 + sp) * MS + t];
        }
        sO[t] = a * INV8 + lpbs[t];
        g_scs[n * MS + t] = b * INV16;
    }
    if (t < 96) {
        const int w = t / 3, i = t - w * 3;
        float a = 0.f, b = 0.f;
        #pragma unroll 8
        for (int u = 0; u < MV; u++) {
            float x = vIn[u * 3 + i];
            a += x * lpWv[u * MV + w];
            b += x * scWv[(u * 4 + sp) * MV + w];
        }
        vO[w * 3 + i] = a * INV_SQRT32;
        g_scv[n * 96 + w * 3 + i] = b * INV_SQRT128;
    }
    __syncthreads();

    if (t < 64) {
        const int w = t;
        float p0 = 0.f, p1 = 0.f, p2 = 0.f, q0 = 0.f, q1 = 0.f, q2 = 0.f;
        #pragma unroll 4
        for (int u = 0; u < 32; u++) {
            float wa = Wvv0[u * 64 + w];
            float wb = Wvv0[(32 + u) * 64 + w];
            float x0 = vO[u * 3], x1 = vO[u * 3 + 1], x2 = vO[u * 3 + 2];
            p0 += x0 * wa; p1 += x1 * wa; p2 += x2 * wa;
            q0 += x0 * wb; q1 += x1 * wb; q2 += x2 * wb;
        }
        float a = 0.f, b = 0.f;
        #pragma unroll 8
        for (int u = 0; u < 64; u++) {
            float x = sO[u];
            a += x * Wss0[u * 64 + w];
            b += x * Wss0[(64 + u) * 64 + w];
        }
        g_zsI[n * 64 + w] = make_float4(p0 * INV_SQRT3, p1 * INV_SQRT3, p2 * INV_SQRT3, a);
        g_zsJ[n * 64 + w] = make_float4(q0 * INV_SQRT3, q1 * INV_SQRT3, q2 * INV_SQRT3, b);
    } else if (t < 96) {
        const int w = t - 64;
        float p0 = 0.f, p1 = 0.f, p2 = 0.f, q0 = 0.f, q1 = 0.f, q2 = 0.f;
        #pragma unroll 4
        for (int u = 0; u < 32; u++) {
            float wa = Wvvg[u * 32 + w];
            float wb = Wvvg[(32 + u) * 32 + w];
            float x0 = vO[u * 3], x1 = vO[u * 3 + 1], x2 = vO[u * 3 + 2];
            p0 += x0 * wa; p1 += x1 * wa; p2 += x2 * wa;
            q0 += x0 * wb; q1 += x1 * wb; q2 += x2 * wb;
        }
        float a = 0.f, b = 0.f;
        #pragma unroll 8
        for (int u = 0; u < 64; u++) {
            float x = sO[u];
            a += x * Wssg[u * 32 + w];
            b += x * Wssg[(64 + u) * 32 + w];
        }
        g_zgI[n * 32 + w] = make_float4(p0 * INV_SQRT3, p1 * INV_SQRT3, p2 * INV_SQRT3, a);
        g_zgJ[n * 32 + w] = make_float4(q0 * INV_SQRT3, q1 * INV_SQRT3, q2 * INV_SQRT3, b);
    } else {
        const int w = t - 96;
        float p0 = 0.f, p1 = 0.f, p2 = 0.f, q0 = 0.f, q1 = 0.f, q2 = 0.f;
        #pragma unroll 4
        for (int u = 0; u < 32; u++) {
            float wa = Wvs1[u * 32 + w];
            float wb = Wvs1[(32 + u) * 32 + w];
            float x0 = vO[u * 3], x1 = vO[u * 3 + 1], x2 = vO[u * 3 + 2];
            p0 += x0 * wa; p1 += x1 * wa; p2 += x2 * wa;
            q0 += x0 * wb; q1 += x1 * wb; q2 += x2 * wb;
        }
        float a = 0.f, b = 0.f;
        #pragma unroll 8
        for (int u = 0; u < 64; u++) {
            float x = sO[u];
            a += x * Wsv1[u * 32 + w];
            b += x * Wsv1[(64 + u) * 32 + w];
        }
        g_svI[n * 32 + w] = make_float4(p0, p1, p2, a);
        g_svJ[n * 32 + w] = make_float4(q0, q1, q2, b);
    }
}

// ---------------- combine kernel (unchanged) ----------------
__global__ __launch_bounds__(128) void k_combine(
    const float* __restrict__ edge_sh, const float* __restrict__ edge_fea,
    const int* __restrict__ edge_index, const float* __restrict__ Wvs1, int E)
{
    __shared__ float sEV[EPB][3][32];
    __shared__ float sWv[32][33];
    __shared__ float sSG[EPB][32];
    __shared__ float sT1[EPB][32];
    __shared__ float sQ [EPB][3][32];
    __shared__ float sSH[EPB][4];
    __shared__ int   sI[EPB], sJ[EPB], sOK[EPB];

    const int t  = threadIdx.x;
    const int e0 = blockIdx.x * EPB;

    if (t < EPB) {
        int eg = e0 + t;
        int ok = (eg < E);
        sOK[t] = ok;
        sI[t]  = ok ? edge_index[eg]     : 0;
        sJ[t]  = ok ? edge_index[E + eg] : 0;
    }
    if (t >= 32 && t < 32 + EPB * 4) {
        int q = t - 32;
        int e = q >> 2, k = q & 3;
        int eg = e0 + e;
        sSH[e][k] = (eg < E) ? edge_sh[eg * 4 + k] : 0.f;
    }
    for (int idx = t; idx < 32 * 32; idx += 128) {
        int u = idx >> 5, w = idx & 31;
        sWv[u][w] = Wvs1[(64 + u) * 32 + w];
    }
    __syncthreads();

    for (int id = t; id < EPB * 96; id += 128) {
        int e = id / 96, c = id - e * 96;
        int u = c / 3, ii = c - u * 3;
        sEV[e][ii][u] = sOK[e] ? edge_fea[(size_t)(e0 + e) * DN + 64 + c] : 0.f;
    }
    __syncthreads();

    if (t < 64) {
        const int w = t;
        #pragma unroll
        for (int e = 0; e < EPB; e++) {
            if (sOK[e]) {
                const int i = sI[e], j = sJ[e];
                float4 pI = __ldg(&g_zsI[i * 64 + w]);
                float4 pJ = __ldg(&g_zsJ[j * 64 + w]);
                float S = __ldg(&g_Ces[(size_t)(e0 + e) * 128 + w]) + pI.w + pJ.w;
                float D = __ldg(&g_Cdd[(size_t)(e0 + e) * 96 + w])
                          + sSH[e][1] * (pI.x + pJ.x)
                          + sSH[e][2] * (pI.y + pJ.y)
                          + sSH[e][3] * (pI.z + pJ.z);
                float z = (sSH[e][0] * S + D) * INV_FAN;
                float val = silu_f(z) * __ldg(&g_WFC[(size_t)(e0 + e) * 96 + w]);
                atomicAdd(&g_ns[i * MS + w], val);
            }
        }
    } else if (t < 96) {
        const int w = t - 64;
        #pragma unroll
        for (int e = 0; e < EPB; e++) {
            const int i = sI[e], j = sJ[e];
            float4 pI = __ldg(&g_zgI[i * 32 + w]);
            float4 pJ = __ldg(&g_zgJ[j * 32 + w]);
            float S = __ldg(&g_Ces[(size_t)(e0 + e) * 128 + 64 + w]) + pI.w + pJ.w;
            float D = __ldg(&g_Cdd[(size_t)(e0 + e) * 96 + 64 + w])
                      + sSH[e][1] * (pI.x + pJ.x)
                      + sSH[e][2] * (pI.y + pJ.y)
                      + sSH[e][3] * (pI.z + pJ.z);
            sSG[e][w] = sigm_f((sSH[e][0] * S + D) * INV_FAN);
        }
    } else {
        const int w = t - 96;
        #pragma unroll
        for (int e = 0; e < EPB; e++) {
            const int i = sI[e], j = sJ[e];
            float4 qI = __ldg(&g_svI[i * 32 + w]);
            float4 qJ = __ldg(&g_svJ[j * 32 + w]);
            sT1[e][w] = __ldg(&g_Ces[(size_t)(e0 + e) * 128 + 96 + w]) + qI.w + qJ.w;
            sQ[e][0][w] = qI.x + qJ.x;
            sQ[e][1][w] = qI.y + qJ.y;
            sQ[e][2][w] = qI.z + qJ.z;
        }
    }
    __syncthreads();

    if (t < 96) {
        const int w = t & 31, ii = t >> 5;
        #pragma unroll
        for (int e = 0; e < EPB; e++) {
            if (sOK[e]) {
                float acc = sQ[e][ii][w];
                #pragma unroll 8
                for (int u = 0; u < 32; u++) acc += sEV[e][ii][u] * sWv[u][w];
                float zv = (sT1[e][w] * sSH[e][1 + ii] + acc * sSH[e][0]) * INV_FAN
                           * sSG[e][w] * __ldg(&g_WFC[(size_t)(e0 + e) * 96 + 64 + w]);
                atomicAdd(&g_nv[sI[e] * 96 + w * 3 + ii], zv);
            }
        }
    }
}

// ---------------- node post (shuffle reduction) ----------------
__global__ __launch_bounds__(96) void k_node_post(
    const float* __restrict__ ppWs, const float* __restrict__ ppbs,
    const float* __restrict__ ppWv, const int* __restrict__ batch)
{
    const int n = blockIdx.x;
    const int t = threadIdx.x;
    const int lane = t & 31, wid = t >> 5;
    __shared__ float sns[MS];
    __shared__ float snv[MV * 3];
    __shared__ float part[3][3];

    if (t < MS) sns[t] = g_ns[n * MS + t];
    snv[t] = g_nv[n * 96 + t];
    __syncthreads();

    float ps = 0.f, ps2 = 0.f, pv2 = 0.f;
    if (t < MS) {
        float a = 0.f;
        #pragma unroll 8
        for (int u = 0; u < MS; u++) a += sns[u] * ppWs[u * MS + t];
        float val = a * INV8 + ppbs[t] + g_scs[n * MS + t];
        g_ps[n * MS + t] = val;
        ps = val; ps2 = val * val;
    }
    {
        const int w = t / 3, i = t - w * 3;
        float a = 0.f;
        #pragma unroll 8
        for (int u = 0; u < MV; u++) a += snv[u * 3 + i] * ppWv[u * MV + w];
        float val = a * INV_SQRT32 + g_scv[n * 96 + t];
        g_pv[n * 96 + t] = val;
        pv2 = val * val;
    }
    #pragma unroll
    for (int o = 16; o; o >>= 1) {
        ps  += __shfl_xor_sync(0xffffffffu, ps,  o);
        ps2 += __shfl_xor_sync(0xffffffffu, ps2, o);
        pv2 += __shfl_xor_sync(0xffffffffu, pv2, o);
    }
    if (lane == 0) { part[wid][0] = ps; part[wid][1] = ps2; part[wid][2] = pv2; }
    __syncthreads();
    if (t == 0) {
        const int g = batch[n];
        float s0 = part[0][0] + part[1][0] + part[2][0];
        float s1 = part[0][1] + part[1][1] + part[2][1];
        float s2 = part[0][2] + part[1][2] + part[2][2];
        atomicAdd(&g_stats[g * 4 + 0], s0 * (1.f / 64.f));
        atomicAdd(&g_stats[g * 4 + 1], s1 * (1.f / 64.f));
        atomicAdd(&g_stats[g * 4 + 2], s2 * (1.f / 96.f));
        atomicAdd(&g_stats[g * 4 + 3], 1.f);
    }
}

// ---------------- group stats finalize ----------------
__global__ void k_stats() {
    const int g = threadIdx.x;
    if (g < NGROUP) {
        float cnt = fmaxf(g_stats[g * 4 + 3], 1.f);
        float mu  = g_stats[g * 4 + 0] / cnt;
        float vs  = fmaxf(g_stats[g * 4 + 1] / cnt - mu * mu, 0.f);
        float vv  = g_stats[g * 4 + 2] / cnt;
        g_norm[g * 3 + 0] = mu;
        g_norm[g * 3 + 1] = rsqrtf(vs + LN_EPS);
        g_norm[g * 3 + 2] = rsqrtf(vv + LN_EPS);
    }
}

// ---------------- finalize output ----------------
__global__ void k_finalize(
    const float* __restrict__ nf, const int* __restrict__ batch,
    const float* __restrict__ lnws, const float* __restrict__ lnbs,
    const float* __restrict__ lnwv, float* __restrict__ out, int N)
{
    const int total = N * DN;
    for (int idx = blockIdx.x * blockDim.x + threadIdx.x; idx < total;
         idx += gridDim.x * blockDim.x) {
        const int n = idx / DN;
        const int c = idx - n * DN;
        const int g = batch[n];
        float o;
        if (c < MS) {
            float mu = g_norm[g * 3 + 0], is = g_norm[g * 3 + 1];
            o = nf[idx] + (g_ps[n * MS + c] - mu) * is * lnws[c] + lnbs[c];
        } else {
            const int u3 = c - MS;
            float iv = g_norm[g * 3 + 2];
            o = nf[idx] + g_pv[n * 96 + u3] * iv * lnwv[u3 / 3];
        }
        out[idx] = o;
    }
}

// ---------------- launch ----------------
extern "C" void kernel_launch(void* const* d_in, const int* in_sizes, int n_in,
                              void* d_out, int out_size)
{
    const float* node_fea = (const float*)d_in[0];
    const float* onehot   = (const float*)d_in[1];
    const float* edge_sh  = (const float*)d_in[2];
    const float* edge_fea = (const float*)d_in[3];
    const float* ele      = (const float*)d_in[4];
    const int*   edge_idx = (const int*)  d_in[5];
    const int*   batch    = (const int*)  d_in[6];
    const float* lpWs = (const float*)d_in[7];
    const float* lpbs = (const float*)d_in[8];
    const float* lpWv = (const float*)d_in[9];
    const float* ppWs = (const float*)d_in[10];
    const float* ppbs = (const float*)d_in[11];
    const float* ppWv = (const float*)d_in[12];
    const float* scWs = (const float*)d_in[13];
    const float* scWv = (const float*)d_in[14];
    const float* Wss0 = (const float*)d_in[15];
    const float* Wvv0 = (const float*)d_in[16];
    const float* Wssg = (const float*)d_in[17];
    const float* Wvvg = (const float*)d_in[18];
    const float* Wsv1 = (const float*)d_in[19];
    const float* Wvs1 = (const float*)d_in[20];
    const float* fW1  = (const float*)d_in[21];
    const float* fb1  = (const float*)d_in[22];
    const float* fW2  = (const float*)d_in[23];
    const float* fb2  = (const float*)d_in[24];
    const float* fW3  = (const float*)d_in[25];
    const float* fb3  = (const float*)d_in[26];
    const float* lnws = (const float*)d_in[27];
    const float* lnbs = (const float*)d_in[28];
    const float* lnwv = (const float*)d_in[29];
    float* out = (float*)d_out;

    const int N = in_sizes[0] / DN;
    const int E = in_sizes[2] / 4;

    const int smem_fc   = (8448 * 2) * 4 + 2 * (4 * 16 * 68) * 4;   // 102400 B
    const int smem_esdd = (8704 * 2) * 4 + (64 * 36) * 4;           //  78848 B
    cudaFuncSetAttribute(k_fc,   cudaFuncAttributeMaxDynamicSharedMemorySize, smem_fc);
    cudaFuncSetAttribute(k_esdd, cudaFuncAttributeMaxDynamicSharedMemorySize, smem_esdd);

    const int gemm_grid = (E + 63) / 64;
    const int zt = N * DN + NGROUP * 4;

    k_zero<<<(zt + 255) / 256, 256>>>(N);
    k_prepW<<<(64 * 128 + 32 * 96 + 255) / 256, 256>>>(Wss0, Wssg, Wsv1, Wvv0, Wvvg);
    k_node_pre<<<N, 128>>>(node_fea, onehot, lpWs, lpbs, lpWv, scWs, scWv,
                           Wss0, Wvv0, Wssg, Wvvg, Wsv1, Wvs1);
    k_fc  <<<gemm_grid, 128, smem_fc>>>(ele, fW1, fb1, fW2, fb2, fW3, fb3, E);
    k_esdd<<<gemm_grid, 128, smem_esdd>>>(edge_fea, edge_sh, E);
    k_combine<<<(E + EPB - 1) / EPB, 128>>>(edge_sh, edge_fea, edge_idx, Wvs1, E);
    k_node_post<<<N, 96>>>(ppWs, ppbs, ppWv, batch);
    k_stats<<<1, 32>>>();
    k_finalize<<<(N * DN + 255) / 256, 256>>>(node_fea, batch, lnws, lnbs, lnwv, out, N);
}

// round 7
// speedup vs baseline: 1.3741x; 1.3741x over previous
#include <cuda_runtime.h>
#include <math.h>

// ---------------- problem constants ----------------
#define DN     160
#define MS     64
#define MV     32
#define NGROUP 16
#define FCIN   128
#define MAXN   10000
#define MAXE   320000
#define EPB    8

#define INV8        0.125f
#define INV16       0.0625f
#define INV_SQRT32  0.17677669529663687f
#define INV_SQRT128 0.08838834764831845f
#define INV_SQRT3   0.5773502691896258f
#define INV_FAN     0.05892556509887896f
#define LN_EPS      1e-5f

// ---------------- device scratch ----------------
__device__ float g_scs[MAXN * MS];
__device__ float g_scv[MAXN * MV * 3];
__device__ float g_ns [MAXN * MS];
__device__ float g_nv [MAXN * MV * 3];
__device__ float g_ps [MAXN * MS];
__device__ float g_pv [MAXN * MV * 3];
__device__ float g_stats[NGROUP * 4];
__device__ float g_norm [NGROUP * 3];

// per-node precomputed partials {P_c0,P_c1,P_c2, A}
__device__ float4 g_zsI[MAXN * 64];
__device__ float4 g_zsJ[MAXN * 64];
__device__ float4 g_zgI[MAXN * 32];
__device__ float4 g_zgJ[MAXN * 32];
__device__ float4 g_svI[MAXN * 32];
__device__ float4 g_svJ[MAXN * 32];

// per-edge GEMM intermediates
__device__ float g_H1 [(size_t)MAXE * 64];
__device__ float g_H2 [(size_t)MAXE * 64];
__device__ float g_WFC[(size_t)MAXE * 96];
__device__ float g_Ces[(size_t)MAXE * 128];
__device__ float g_Cdd[(size_t)MAXE * 96];
// concatenated weights
__device__ float g_Wes[64 * 128];
__device__ float g_Wdd[32 * 96];

__device__ __forceinline__ float silu_f(float x) { return x / (1.f + __expf(-x)); }
__device__ __forceinline__ float sigm_f(float x) { return 1.f / (1.f + __expf(-x)); }

__device__ __forceinline__ unsigned int f2tf32(float x) {
    unsigned int r;
    asm("cvt.rna.tf32.f32 %0, %1;" : "=r"(r) : "f"(x));
    return r;
}
__device__ __forceinline__ void mma8(float* c, unsigned int a0, unsigned int a1,
                                     unsigned int a2, unsigned int a3,
                                     unsigned int b0, unsigned int b1) {
    asm volatile(
        "mma.sync.aligned.m16n8k8.row.col.f32.tf32.tf32.f32 "
        "{%0,%1,%2,%3}, {%4,%5,%6,%7}, {%8,%9}, {%0,%1,%2,%3};"
        : "+f"(c[0]), "+f"(c[1]), "+f"(c[2]), "+f"(c[3])
        : "r"(a0), "r"(a1), "r"(a2), "r"(a3), "r"(b0), "r"(b1));
}

// load W[K][N] into smem as hi/lo tf32, layout [N][K+4], 256 threads
template<int K, int N>
__device__ __forceinline__ void load_w(unsigned* wHi, unsigned* wLo,
                                       const float* __restrict__ W, int t) {
    constexpr int KP = K + 4;
    for (int idx = t; idx < K * N; idx += 256) {
        int k = idx / N, n = idx - k * N;
        float w = W[idx];
        unsigned hi = f2tf32(w);
        wHi[n * KP + k] = hi;
        wLo[n * KP + k] = f2tf32(w - __uint_as_float(hi));
    }
}

// 3xTF32 accumulate: rows A0 (r), A1 (r+8), contiguous cols
template<int K, int NB>
__device__ __forceinline__ void mma_stage(const unsigned* __restrict__ wHi,
                                          const unsigned* __restrict__ wLo,
                                          const float* __restrict__ A0,
                                          const float* __restrict__ A1,
                                          float acc[NB][4], int lane) {
    constexpr int KP = K + 4;
    #pragma unroll
    for (int kb = 0; kb < K / 8; kb++) {
        const int c = kb * 8 + (lane & 3);
        float a0 = A0[c],     a1 = A1[c];
        float a2 = A0[c + 4], a3 = A1[c + 4];
        unsigned h0 = f2tf32(a0), h1 = f2tf32(a1), h2 = f2tf32(a2), h3 = f2tf32(a3);
        unsigned l0 = f2tf32(a0 - __uint_as_float(h0));
        unsigned l1 = f2tf32(a1 - __uint_as_float(h1));
        unsigned l2 = f2tf32(a2 - __uint_as_float(h2));
        unsigned l3 = f2tf32(a3 - __uint_as_float(h3));
        const int koff = kb * 8 + (lane & 3);
        const int nbase = lane >> 2;
        #pragma unroll
        for (int nb = 0; nb < NB; nb++) {
            int off = (nb * 8 + nbase) * KP + koff;
            unsigned bh0 = wHi[off], bh1 = wHi[off + 4];
            unsigned bl0 = wLo[off], bl1 = wLo[off + 4];
            mma8(acc[nb], h0, h1, h2, h3, bh0, bh1);
            mma8(acc[nb], l0, l1, l2, l3, bh0, bh1);
            mma8(acc[nb], h0, h1, h2, h3, bl0, bl1);
        }
    }
}

// ---------------- zero scratch ----------------
__global__ void k_zero(int N) {
    int tot = N * DN + NGROUP * 4;
    for (int i = blockIdx.x * blockDim.x + threadIdx.x; i < tot; i += gridDim.x * blockDim.x) {
        if (i < N * MS)      g_ns[i] = 0.f;
        else if (i < N * DN) g_nv[i - N * MS] = 0.f;
        else                 g_stats[i - N * DN] = 0.f;
    }
}

// ---------------- concat-weight prep ----------------
__global__ void k_prepW(const float* __restrict__ Wss0, const float* __restrict__ Wssg,
                        const float* __restrict__ Wsv1, const float* __restrict__ Wvv0,
                        const float* __restrict__ Wvvg) {
    int t = blockIdx.x * blockDim.x + threadIdx.x;
    if (t < 64 * 128) {
        int u = t >> 7, n = t & 127;
        float v;
        if (n < 64)      v = Wss0[(128 + u) * 64 + n];
        else if (n < 96) v = Wssg[(128 + u) * 32 + (n - 64)];
        else             v = Wsv1[(128 + u) * 32 + (n - 96)];
        g_Wes[t] = v;
    } else if (t < 64 * 128 + 32 * 96) {
        int i = t - 64 * 128;
        int u = i / 96, n = i - u * 96;
        g_Wdd[i] = (n < 64) ? Wvv0[(64 + u) * 64 + n] : Wvvg[(64 + u) * 32 + (n - 64)];
    }
}

// ---------------- generic 3xTF32 GEMM, 256 threads, 128 rows/block ----------------
template<int K, int N, int ACT, int HASB>
__global__ void __launch_bounds__(256) k_mma(
    const float* __restrict__ A, long lda,
    const float* __restrict__ W, const float* __restrict__ bias,
    float* __restrict__ C, int E)
{
    constexpr int NB = N / 8;
    extern __shared__ unsigned smw[];
    unsigned* sHi = smw;
    unsigned* sLo = smw + N * (K + 4);

    const int t = threadIdx.x;
    const int lane = t & 31, warp = t >> 5;

    load_w<K, N>(sHi, sLo, W, t);
    __syncthreads();

    const int r0 = blockIdx.x * 128 + warp * 16 + (lane >> 2);
    const int r1 = r0 + 8;
    const long ar0 = (long)min(r0, E - 1) * lda;
    const long ar1 = (long)min(r1, E - 1) * lda;

    float acc[NB][4];
    #pragma unroll
    for (int nb = 0; nb < NB; nb++) {
        acc[nb][0] = 0.f; acc[nb][1] = 0.f; acc[nb][2] = 0.f; acc[nb][3] = 0.f;
    }
    mma_stage<K, NB>(sHi, sLo, A + ar0, A + ar1, acc, lane);

    #pragma unroll
    for (int nb = 0; nb < NB; nb++) {
        int n = nb * 8 + 2 * (lane & 3);
        float b0 = 0.f, b1 = 0.f;
        if (HASB) { b0 = __ldg(&bias[n]); b1 = __ldg(&bias[n + 1]); }
        float v0 = acc[nb][0] + b0, v1 = acc[nb][1] + b1;
        float v2 = acc[nb][2] + b0, v3 = acc[nb][3] + b1;
        if (ACT) { v0 = silu_f(v0); v1 = silu_f(v1); v2 = silu_f(v2); v3 = silu_f(v3); }
        if (r0 < E) *reinterpret_cast<float2*>(&C[(long)r0 * N + n]) = make_float2(v0, v1);
        if (r1 < E) *reinterpret_cast<float2*>(&C[(long)r1 * N + n]) = make_float2(v2, v3);
    }
}

// ---------------- fused dd-prep + Cdd GEMM: [128,32]@[32,96] ----------------
__global__ void __launch_bounds__(256) k_cdd(
    const float* __restrict__ edge_fea, const float* __restrict__ edge_sh, int E)
{
    extern __shared__ unsigned smraw[];
    unsigned* wHi = smraw;                     // 96*36
    unsigned* wLo = smraw + 96 * 36;
    float* DD = (float*)(smraw + 2 * 96 * 36); // [128][36]

    const int t = threadIdx.x;
    const int lane = t & 31, warp = t >> 5;
    const int e0 = blockIdx.x * 128;

    load_w<32, 96>(wHi, wLo, g_Wdd, t);

    for (int idx = t; idx < 128 * 32; idx += 256) {
        int e = idx >> 5, u = idx & 31;
        int eg = e0 + e;
        float v = 0.f;
        if (eg < E) {
            const float* ev = edge_fea + (size_t)eg * DN + 64 + u * 3;
            v = (ev[0] * edge_sh[eg * 4 + 1] + ev[1] * edge_sh[eg * 4 + 2] +
                 ev[2] * edge_sh[eg * 4 + 3]) * INV_SQRT3;
        }
        DD[e * 36 + u] = v;
    }
    __syncthreads();

    const int r0 = e0 + warp * 16 + (lane >> 2);
    const int r1 = r0 + 8;
    const float* A0 = DD + (warp * 16 + (lane >> 2)) * 36;
    const float* A1 = A0 + 8 * 36;

    float acc[12][4];
    #pragma unroll
    for (int nb = 0; nb < 12; nb++) { acc[nb][0]=0.f; acc[nb][1]=0.f; acc[nb][2]=0.f; acc[nb][3]=0.f; }
    mma_stage<32, 12>(wHi, wLo, A0, A1, acc, lane);

    #pragma unroll
    for (int nb = 0; nb < 12; nb++) {
        int n = nb * 8 + 2 * (lane & 3);
        if (r0 < E) *reinterpret_cast<float2*>(&g_Cdd[(long)r0 * 96 + n]) =
            make_float2(acc[nb][0], acc[nb][1]);
        if (r1 < E) *reinterpret_cast<float2*>(&g_Cdd[(long)r1 * 96 + n]) =
            make_float2(acc[nb][2], acc[nb][3]);
    }
}

// ---------------- node pre ----------------
__global__ __launch_bounds__(128) void k_node_pre(
    const float* __restrict__ nf, const float* __restrict__ onehot,
    const float* __restrict__ lpWs, const float* __restrict__ lpbs,
    const float* __restrict__ lpWv,
    const float* __restrict__ scWs, const float* __restrict__ scWv,
    const float* __restrict__ Wss0, const float* __restrict__ Wvv0,
    const float* __restrict__ Wssg, const float* __restrict__ Wvvg,
    const float* __restrict__ Wsv1, const float* __restrict__ Wvs1)
{
    const int n = blockIdx.x;
    const int t = threadIdx.x;
    __shared__ float sIn[MS];
    __shared__ float vIn[MV * 3];
    __shared__ float sO [MS];
    __shared__ float vO [MV * 3];
    __shared__ int ssp;

    if (t < MS) sIn[t] = nf[n * DN + t];
    if (t < 96) vIn[t] = nf[n * DN + MS + t];
    if (t == 0) {
        int sp = 0; float best = onehot[n * 4];
        #pragma unroll
        for (int k = 1; k < 4; k++) { float v = onehot[n * 4 + k]; if (v > best) { best = v; sp = k; } }
        ssp = sp;
    }
    __syncthreads();
    const int sp = ssp;

    if (t < MS) {
        float a = 0.f, b = 0.f;
        #pragma unroll 8
        for (int u = 0; u < MS; u++) {
            float x = sIn[u];
            a += x * lpWs[u * MS + t];
            b += x * scWs[(u * 4 + sp) * MS + t];
        }
        sO[t] = a * INV8 + lpbs[t];
        g_scs[n * MS + t] = b * INV16;
    }
    if (t < 96) {
        const int w = t / 3, i = t - w * 3;
        float a = 0.f, b = 0.f;
        #pragma unroll 8
        for (int u = 0; u < MV; u++) {
            float x = vIn[u * 3 + i];
            a += x * lpWv[u * MV + w];
            b += x * scWv[(u * 4 + sp) * MV + w];
        }
        vO[w * 3 + i] = a * INV_SQRT32;
        g_scv[n * 96 + w * 3 + i] = b * INV_SQRT128;
    }
    __syncthreads();

    if (t < 64) {
        const int w = t;
        float p0 = 0.f, p1 = 0.f, p2 = 0.f, q0 = 0.f, q1 = 0.f, q2 = 0.f;
        #pragma unroll 4
        for (int u = 0; u < 32; u++) {
            float wa = Wvv0[u * 64 + w];
            float wb = Wvv0[(32 + u) * 64 + w];
            float x0 = vO[u * 3], x1 = vO[u * 3 + 1], x2 = vO[u * 3 + 2];
            p0 += x0 * wa; p1 += x1 * wa; p2 += x2 * wa;
            q0 += x0 * wb; q1 += x1 * wb; q2 += x2 * wb;
        }
        float a = 0.f, b = 0.f;
        #pragma unroll 8
        for (int u = 0; u < 64; u++) {
            float x = sO[u];
            a += x * Wss0[u * 64 + w];
            b += x * Wss0[(64 + u) * 64 + w];
        }
        g_zsI[n * 64 + w] = make_float4(p0 * INV_SQRT3, p1 * INV_SQRT3, p2 * INV_SQRT3, a);
        g_zsJ[n * 64 + w] = make_float4(q0 * INV_SQRT3, q1 * INV_SQRT3, q2 * INV_SQRT3, b);
    } else if (t < 96) {
        const int w = t - 64;
        float p0 = 0.f, p1 = 0.f, p2 = 0.f, q0 = 0.f, q1 = 0.f, q2 = 0.f;
        #pragma unroll 4
        for (int u = 0; u < 32; u++) {
            float wa = Wvvg[u * 32 + w];
            float wb = Wvvg[(32 + u) * 32 + w];
            float x0 = vO[u * 3], x1 = vO[u * 3 + 1], x2 = vO[u * 3 + 2];
            p0 += x0 * wa; p1 += x1 * wa; p2 += x2 * wa;
            q0 += x0 * wb; q1 += x1 * wb; q2 += x2 * wb;
        }
        float a = 0.f, b = 0.f;
        #pragma unroll 8
        for (int u = 0; u < 64; u++) {
            float x = sO[u];
            a += x * Wssg[u * 32 + w];
            b += x * Wssg[(64 + u) * 32 + w];
        }
        g_zgI[n * 32 + w] = make_float4(p0 * INV_SQRT3, p1 * INV_SQRT3, p2 * INV_SQRT3, a);
        g_zgJ[n * 32 + w] = make_float4(q0 * INV_SQRT3, q1 * INV_SQRT3, q2 * INV_SQRT3, b);
    } else {
        const int w = t - 96;
        float p0 = 0.f, p1 = 0.f, p2 = 0.f, q0 = 0.f, q1 = 0.f, q2 = 0.f;
        #pragma unroll 4
        for (int u = 0; u < 32; u++) {
            float wa = Wvs1[u * 32 + w];
            float wb = Wvs1[(32 + u) * 32 + w];
            float x0 = vO[u * 3], x1 = vO[u * 3 + 1], x2 = vO[u * 3 + 2];
            p0 += x0 * wa; p1 += x1 * wa; p2 += x2 * wa;
            q0 += x0 * wb; q1 += x1 * wb; q2 += x2 * wb;
        }
        float a = 0.f, b = 0.f;
        #pragma unroll 8
        for (int u = 0; u < 64; u++) {
            float x = sO[u];
            a += x * Wsv1[u * 32 + w];
            b += x * Wsv1[(64 + u) * 32 + w];
        }
        g_svI[n * 32 + w] = make_float4(p0, p1, p2, a);
        g_svJ[n * 32 + w] = make_float4(q0, q1, q2, b);
    }
}

// ---------------- combine kernel ----------------
__global__ __launch_bounds__(128) void k_combine(
    const float* __restrict__ edge_sh, const float* __restrict__ edge_fea,
    const int* __restrict__ edge_index, const float* __restrict__ Wvs1, int E)
{
    __shared__ float sEV[EPB][3][32];
    __shared__ float sWv[32][33];
    __shared__ float sSG[EPB][32];
    __shared__ float sT1[EPB][32];
    __shared__ float sQ [EPB][3][32];
    __shared__ float sSH[EPB][4];
    __shared__ int   sI[EPB], sJ[EPB], sOK[EPB];

    const int t  = threadIdx.x;
    const int e0 = blockIdx.x * EPB;

    if (t < EPB) {
        int eg = e0 + t;
        int ok = (eg < E);
        sOK[t] = ok;
        sI[t]  = ok ? edge_index[eg]     : 0;
        sJ[t]  = ok ? edge_index[E + eg] : 0;
    }
    if (t >= 32 && t < 32 + EPB * 4) {
        int q = t - 32;
        int e = q >> 2, k = q & 3;
        int eg = e0 + e;
        sSH[e][k] = (eg < E) ? edge_sh[eg * 4 + k] : 0.f;
    }
    for (int idx = t; idx < 32 * 32; idx += 128) {
        int u = idx >> 5, w = idx & 31;
        sWv[u][w] = Wvs1[(64 + u) * 32 + w];
    }
    __syncthreads();

    for (int id = t; id < EPB * 96; id += 128) {
        int e = id / 96, c = id - e * 96;
        int u = c / 3, ii = c - u * 3;
        sEV[e][ii][u] = sOK[e] ? edge_fea[(size_t)(e0 + e) * DN + 64 + c] : 0.f;
    }
    __syncthreads();

    if (t < 64) {
        const int w = t;
        #pragma unroll
        for (int e = 0; e < EPB; e++) {
            if (sOK[e]) {
                const int i = sI[e], j = sJ[e];
                float4 pI = __ldg(&g_zsI[i * 64 + w]);
                float4 pJ = __ldg(&g_zsJ[j * 64 + w]);
                float S = __ldg(&g_Ces[(size_t)(e0 + e) * 128 + w]) + pI.w + pJ.w;
                float D = __ldg(&g_Cdd[(size_t)(e0 + e) * 96 + w])
                          + sSH[e][1] * (pI.x + pJ.x)
                          + sSH[e][2] * (pI.y + pJ.y)
                          + sSH[e][3] * (pI.z + pJ.z);
                float z = (sSH[e][0] * S + D) * INV_FAN;
                float val = silu_f(z) * __ldg(&g_WFC[(size_t)(e0 + e) * 96 + w]);
                atomicAdd(&g_ns[i * MS + w], val);
            }
        }
    } else if (t < 96) {
        const int w = t - 64;
        #pragma unroll
        for (int e = 0; e < EPB; e++) {
            const int i = sI[e], j = sJ[e];
            float4 pI = __ldg(&g_zgI[i * 32 + w]);
            float4 pJ = __ldg(&g_zgJ[j * 32 + w]);
            float S = __ldg(&g_Ces[(size_t)(e0 + e) * 128 + 64 + w]) + pI.w + pJ.w;
            float D = __ldg(&g_Cdd[(size_t)(e0 + e) * 96 + 64 + w])
                      + sSH[e][1] * (pI.x + pJ.x)
                      + sSH[e][2] * (pI.y + pJ.y)
                      + sSH[e][3] * (pI.z + pJ.z);
            sSG[e][w] = sigm_f((sSH[e][0] * S + D) * INV_FAN);
        }
    } else {
        const int w = t - 96;
        #pragma unroll
        for (int e = 0; e < EPB; e++) {
            const int i = sI[e], j = sJ[e];
            float4 qI = __ldg(&g_svI[i * 32 + w]);
            float4 qJ = __ldg(&g_svJ[j * 32 + w]);
            sT1[e][w] = __ldg(&g_Ces[(size_t)(e0 + e) * 128 + 96 + w]) + qI.w + qJ.w;
            sQ[e][0][w] = qI.x + qJ.x;
            sQ[e][1][w] = qI.y + qJ.y;
            sQ[e][2][w] = qI.z + qJ.z;
        }
    }
    __syncthreads();

    if (t < 96) {
        const int w = t & 31, ii = t >> 5;
        #pragma unroll
        for (int e = 0; e < EPB; e++) {
            if (sOK[e]) {
                float acc = sQ[e][ii][w];
                #pragma unroll 8
                for (int u = 0; u < 32; u++) acc += sEV[e][ii][u] * sWv[u][w];
                float zv = (sT1[e][w] * sSH[e][1 + ii] + acc * sSH[e][0]) * INV_FAN
                           * sSG[e][w] * __ldg(&g_WFC[(size_t)(e0 + e) * 96 + 64 + w]);
                atomicAdd(&g_nv[sI[e] * 96 + w * 3 + ii], zv);
            }
        }
    }
}

// ---------------- node post (shuffle reduction) ----------------
__global__ __launch_bounds__(96) void k_node_post(
    const float* __restrict__ ppWs, const float* __restrict__ ppbs,
    const float* __restrict__ ppWv, const int* __restrict__ batch)
{
    const int n = blockIdx.x;
    const int t = threadIdx.x;
    const int lane = t & 31, wid = t >> 5;
    __shared__ float sns[MS];
    __shared__ float snv[MV * 3];
    __shared__ float part[3][3];

    if (t < MS) sns[t] = g_ns[n * MS + t];
    snv[t] = g_nv[n * 96 + t];
    __syncthreads();

    float ps = 0.f, ps2 = 0.f, pv2 = 0.f;
    if (t < MS) {
        float a = 0.f;
        #pragma unroll 8
        for (int u = 0; u < MS; u++) a += sns[u] * ppWs[u * MS + t];
        float val = a * INV8 + ppbs[t] + g_scs[n * MS + t];
        g_ps[n * MS + t] = val;
        ps = val; ps2 = val * val;
    }
    {
        const int w = t / 3, i = t - w * 3;
        float a = 0.f;
        #pragma unroll 8
        for (int u = 0; u < MV; u++) a += snv[u * 3 + i] * ppWv[u * MV + w];
        float val = a * INV_SQRT32 + g_scv[n * 96 + t];
        g_pv[n * 96 + t] = val;
        pv2 = val * val;
    }
    #pragma unroll
    for (int o = 16; o; o >>= 1) {
        ps  += __shfl_xor_sync(0xffffffffu, ps,  o);
        ps2 += __shfl_xor_sync(0xffffffffu, ps2, o);
        pv2 += __shfl_xor_sync(0xffffffffu, pv2, o);
    }
    if (lane == 0) { part[wid][0] = ps; part[wid][1] = ps2; part[wid][2] = pv2; }
    __syncthreads();
    if (t == 0) {
        const int g = batch[n];
        float s0 = part[0][0] + part[1][0] + part[2][0];
        float s1 = part[0][1] + part[1][1] + part[2][1];
        float s2 = part[0][2] + part[1][2] + part[2][2];
        atomicAdd(&g_stats[g * 4 + 0], s0 * (1.f / 64.f));
        atomicAdd(&g_stats[g * 4 + 1], s1 * (1.f / 64.f));
        atomicAdd(&g_stats[g * 4 + 2], s2 * (1.f / 96.f));
        atomicAdd(&g_stats[g * 4 + 3], 1.f);
    }
}

// ---------------- group stats finalize ----------------
__global__ void k_stats() {
    const int g = threadIdx.x;
    if (g < NGROUP) {
        float cnt = fmaxf(g_stats[g * 4 + 3], 1.f);
        float mu  = g_stats[g * 4 + 0] / cnt;
        float vs  = fmaxf(g_stats[g * 4 + 1] / cnt - mu * mu, 0.f);
        float vv  = g_stats[g * 4 + 2] / cnt;
        g_norm[g * 3 + 0] = mu;
        g_norm[g * 3 + 1] = rsqrtf(vs + LN_EPS);
        g_norm[g * 3 + 2] = rsqrtf(vv + LN_EPS);
    }
}

// ---------------- finalize output ----------------
__global__ void k_finalize(
    const float* __restrict__ nf, const int* __restrict__ batch,
    const float* __restrict__ lnws, const float* __restrict__ lnbs,
    const float* __restrict__ lnwv, float* __restrict__ out, int N)
{
    const int total = N * DN;
    for (int idx = blockIdx.x * blockDim.x + threadIdx.x; idx < total;
         idx += gridDim.x * blockDim.x) {
        const int n = idx / DN;
        const int c = idx - n * DN;
        const int g = batch[n];
        float o;
        if (c < MS) {
            float mu = g_norm[g * 3 + 0], is = g_norm[g * 3 + 1];
            o = nf[idx] + (g_ps[n * MS + c] - mu) * is * lnws[c] + lnbs[c];
        } else {
            const int u3 = c - MS;
            float iv = g_norm[g * 3 + 2];
            o = nf[idx] + g_pv[n * 96 + u3] * iv * lnwv[u3 / 3];
        }
        out[idx] = o;
    }
}

// ---------------- launch ----------------
extern "C" void kernel_launch(void* const* d_in, const int* in_sizes, int n_in,
                              void* d_out, int out_size)
{
    const float* node_fea = (const float*)d_in[0];
    const float* onehot   = (const float*)d_in[1];
    const float* edge_sh  = (const float*)d_in[2];
    const float* edge_fea = (const float*)d_in[3];
    const float* ele      = (const float*)d_in[4];
    const int*   edge_idx = (const int*)  d_in[5];
    const int*   batch    = (const int*)  d_in[6];
    const float* lpWs = (const float*)d_in[7];
    const float* lpbs = (const float*)d_in[8];
    const float* lpWv = (const float*)d_in[9];
    const float* ppWs = (const float*)d_in[10];
    const float* ppbs = (const float*)d_in[11];
    const float* ppWv = (const float*)d_in[12];
    const float* scWs = (const float*)d_in[13];
    const float* scWv = (const float*)d_in[14];
    const float* Wss0 = (const float*)d_in[15];
    const float* Wvv0 = (const float*)d_in[16];
    const float* Wssg = (const float*)d_in[17];
    const float* Wvvg = (const float*)d_in[18];
    const float* Wsv1 = (const float*)d_in[19];
    const float* Wvs1 = (const float*)d_in[20];
    const float* fW1  = (const float*)d_in[21];
    const float* fb1  = (const float*)d_in[22];
    const float* fW2  = (const float*)d_in[23];
    const float* fb2  = (const float*)d_in[24];
    const float* fW3  = (const float*)d_in[25];
    const float* fb3  = (const float*)d_in[26];
    const float* lnws = (const float*)d_in[27];
    const float* lnbs = (const float*)d_in[28];
    const float* lnwv = (const float*)d_in[29];
    float* out = (float*)d_out;

    const int N = in_sizes[0] / DN;
    const int E = in_sizes[2] / 4;

    float *pH1, *pH2, *pWFC, *pCes, *pWes;
    cudaGetSymbolAddress((void**)&pH1,  g_H1);
    cudaGetSymbolAddress((void**)&pH2,  g_H2);
    cudaGetSymbolAddress((void**)&pWFC, g_WFC);
    cudaGetSymbolAddress((void**)&pCes, g_Ces);
    cudaGetSymbolAddress((void**)&pWes, g_Wes);

    auto smem_of = [](int Kk, int Nn) { return 2 * Nn * (Kk + 4) * (int)sizeof(float); };
    const int smem_cdd = smem_of(32, 96) + 128 * 36 * (int)sizeof(float);
    cudaFuncSetAttribute(k_mma<128, 64, 1, 1>, cudaFuncAttributeMaxDynamicSharedMemorySize, smem_of(128, 64));
    cudaFuncSetAttribute(k_mma< 64, 64, 1, 1>, cudaFuncAttributeMaxDynamicSharedMemorySize, smem_of(64, 64));
    cudaFuncSetAttribute(k_mma< 64, 96, 0, 1>, cudaFuncAttributeMaxDynamicSharedMemorySize, smem_of(64, 96));
    cudaFuncSetAttribute(k_mma< 64,128, 0, 0>, cudaFuncAttributeMaxDynamicSharedMemorySize, smem_of(64, 128));
    cudaFuncSetAttribute(k_cdd, cudaFuncAttributeMaxDynamicSharedMemorySize, smem_cdd);

    const int gemm_grid = (E + 127) / 128;
    const int zt = N * DN + NGROUP * 4;

    k_zero<<<(zt + 255) / 256, 256>>>(N);
    k_prepW<<<(64 * 128 + 32 * 96 + 255) / 256, 256>>>(Wss0, Wssg, Wsv1, Wvv0, Wvvg);
    k_node_pre<<<N, 128>>>(node_fea, onehot, lpWs, lpbs, lpWv, scWs, scWv,
                           Wss0, Wvv0, Wssg, Wvvg, Wsv1, Wvs1);

    k_mma<128, 64, 1, 1><<<gemm_grid, 256, smem_of(128, 64)>>>(ele, 128, fW1, fb1, pH1, E);
    k_mma< 64, 64, 1, 1><<<gemm_grid, 256, smem_of(64, 64)>>>(pH1, 64, fW2, fb2, pH2, E);
    k_mma< 64, 96, 0, 1><<<gemm_grid, 256, smem_of(64, 96)>>>(pH2, 64, fW3, fb3, pWFC, E);
    k_mma< 64,128, 0, 0><<<gemm_grid, 256, smem_of(64, 128)>>>(edge_fea, DN, pWes, nullptr, pCes, E);
    k_cdd<<<gemm_grid, 256, smem_cdd>>>(edge_fea, edge_sh, E);

    k_combine<<<(E + EPB - 1) / EPB, 128>>>(edge_sh, edge_fea, edge_idx, Wvs1, E);
    k_node_post<<<N, 96>>>(ppWs, ppbs, ppWv, batch);
    k_stats<<<1, 32>>>();
    k_finalize<<<(N * DN + 255) / 256, 256>>>(node_fea, batch, lnws, lnbs, lnwv, out, N);
}